// round 4
// baseline (speedup 1.0000x reference)
#include <cuda_runtime.h>
#include <math.h>
#include <stdint.h>

#define NQ   10001          // distinct quantized times: floor(t/0.1), t in [0,1000)
#define NQP  10016          // padded to multiple of 32
#define DD   1024
#define RR   256

#define S_STAGES  8         // smem row buffers in scatter pipeline
#define LOOKAHEAD 6         // TMA loads in flight (<= S_STAGES - 2)
#define SROWS     64        // rows per scatter block (B divisible by 64)

// Scratch (device globals — no allocation allowed)
__device__ float g_WeT[RR * DD];        // w_expand transposed [r][d]   (1 MB)
__device__ float g_table[NQ * DD];      // encoding LUT [q][d]          (~41 MB, L2-resident)

// ---------------------------------------------------------------------------
// Packed fp32x2 helpers (sm_103a FFMA2)
__device__ __forceinline__ void fma_f32x2(unsigned long long& d,
                                          unsigned long long a,
                                          unsigned long long b) {
    asm("fma.rn.f32x2 %0, %1, %2, %0;" : "+l"(d) : "l"(a), "l"(b));
}
__device__ __forceinline__ unsigned long long splat_f32(float w) {
    unsigned long long r;
    asm("mov.b64 %0, {%1, %1};" : "=l"(r) : "f"(w));
    return r;
}
__device__ __forceinline__ float lo_f(unsigned long long p) {
    return __uint_as_float((unsigned int)p);
}
__device__ __forceinline__ float hi_f(unsigned long long p) {
    return __uint_as_float((unsigned int)(p >> 32));
}

// ---------------------------------------------------------------------------
// TMA / mbarrier primitives (1D bulk copies — no tensor map needed)
__device__ __forceinline__ uint32_t smem_u32(const void* p) {
    uint32_t a;
    asm("{ .reg .u64 t; cvta.to.shared.u64 t, %1; cvt.u32.u64 %0, t; }"
        : "=r"(a) : "l"(p));
    return a;
}
__device__ __forceinline__ void mbar_init(uint32_t mbar, uint32_t cnt) {
    asm volatile("mbarrier.init.shared.b64 [%0], %1;" :: "r"(mbar), "r"(cnt) : "memory");
}
__device__ __forceinline__ void mbar_expect_tx(uint32_t mbar, uint32_t bytes) {
    asm volatile("mbarrier.arrive.expect_tx.shared.b64 _, [%0], %1;"
                 :: "r"(mbar), "r"(bytes) : "memory");
}
__device__ __forceinline__ void mbar_wait(uint32_t mbar, uint32_t parity) {
    asm volatile(
        "{\n\t"
        ".reg .pred P;\n\t"
        "WL_%=:\n\t"
        "mbarrier.try_wait.parity.acquire.cta.shared::cta.b64 P, [%0], %1, 0x989680;\n\t"
        "@P bra.uni WD_%=;\n\t"
        "bra.uni WL_%=;\n\t"
        "WD_%=:\n\t"
        "}"
        :: "r"(mbar), "r"(parity) : "memory");
}
__device__ __forceinline__ void bulk_g2s(uint32_t dst_smem, const void* src_gmem,
                                         uint32_t bytes, uint32_t mbar) {
    asm volatile(
        "cp.async.bulk.shared::cta.global.mbarrier::complete_tx::bytes [%0], [%1], %2, [%3];"
        :: "r"(dst_smem), "l"(src_gmem), "r"(bytes), "r"(mbar) : "memory");
}
__device__ __forceinline__ void bulk_s2g(void* dst_gmem, uint32_t src_smem,
                                         uint32_t bytes) {
    asm volatile(
        "cp.async.bulk.global.shared::cta.bulk_group [%0], [%1], %2;"
        :: "l"(dst_gmem), "r"(src_smem), "r"(bytes) : "memory");
}
__device__ __forceinline__ void bulk_commit() {
    asm volatile("cp.async.bulk.commit_group;" ::: "memory");
}
template <int N>
__device__ __forceinline__ void bulk_wait_read() {
    asm volatile("cp.async.bulk.wait_group.read %0;" :: "n"(N) : "memory");
}
__device__ __forceinline__ void bulk_wait_all() {
    asm volatile("cp.async.bulk.wait_group 0;" ::: "memory");
}
__device__ __forceinline__ void fence_proxy_async_shared() {
    asm volatile("fence.proxy.async.shared::cta;" ::: "memory");
}

// ---------------------------------------------------------------------------
// Phase 0: tiled transpose w_expand (D,R) -> (R,D); coalesced both sides.
__global__ void k_transpose_we(const float* __restrict__ we) {
    __shared__ float tile[32][33];
    int tx = threadIdx.x, ty = threadIdx.y;
    int r0 = blockIdx.x * 32, d0 = blockIdx.y * 32;
#pragma unroll
    for (int k = 0; k < 32; k += 8)
        tile[ty + k][tx] = we[(d0 + ty + k) * RR + (r0 + tx)];
    __syncthreads();
#pragma unroll
    for (int k = 0; k < 32; k += 8)
        g_WeT[(r0 + ty + k) * DD + (d0 + tx)] = tile[tx][ty + k];
}

// ---------------------------------------------------------------------------
// Phase 1 (fused): red tile in smem, then table = red @ WeT + web via FFMA2.
// Block 256 thr; tile 32 q x 256 d; thread 4 q-pairs x 4 d. grid (313, 4).
__global__ void __launch_bounds__(256) k_build_table(const float* __restrict__ wr,
                                                     const float* __restrict__ wrb,
                                                     const float* __restrict__ web) {
    __shared__ float sRed[RR * 32];   // [r][q_local], 32 KB
    __shared__ float sWr[RR], sWrb[RR];

    int tid = threadIdx.x;
    int qb0 = blockIdx.x * 32;

    if (tid < RR) { sWr[tid] = wr[tid]; sWrb[tid] = wrb[tid]; }
    __syncthreads();

#pragma unroll 4
    for (int i = tid; i < RR * 32; i += 256) {
        int r  = i >> 5;
        int ql = i & 31;
        int qc = min(qb0 + ql, NQ - 1);           // pad clamped (never stored)
        float tq  = (float)qc * 0.1f;             // matches floor(t/0.1f)*0.1f
        float arg = fmaf(tq, sWr[r], sWrb[r]);
        // Cody-Waite 2*pi reduction (|arg| <= ~153): exact under fast-math
        float k   = rintf(arg * 0.15915494309189535f);
        float red = fmaf(-k, 6.28125f, arg);
        red       = fmaf(-k, 1.9353071795864769e-3f, red);
        float v   = cosf(red);
        sRed[r * 32 + ql] = v > 0.0f ? v : 0.0f;
    }
    __syncthreads();

    int dt = tid & 63;
    int qg = tid >> 6;
    int db = blockIdx.y * 256 + dt * 4;

    unsigned long long acc[4][4];
#pragma unroll
    for (int p = 0; p < 4; ++p)
#pragma unroll
        for (int j = 0; j < 4; ++j) acc[p][j] = 0ULL;

    const float4* WeT4 = (const float4*)g_WeT;
    const ulonglong2* sRed2 = (const ulonglong2*)sRed;

#pragma unroll 4
    for (int r = 0; r < RR; ++r) {
        float4 w = WeT4[(r * DD + db) >> 2];          // coalesced LDG.128
        unsigned long long wp[4] = { splat_f32(w.x), splat_f32(w.y),
                                     splat_f32(w.z), splat_f32(w.w) };
        int sb = (r * 32 + qg * 8) >> 2;              // warp-uniform broadcast
        ulonglong2 y0 = sRed2[sb];
        ulonglong2 y1 = sRed2[sb + 1];
        unsigned long long rp[4] = { y0.x, y0.y, y1.x, y1.y };
#pragma unroll
        for (int p = 0; p < 4; ++p)
#pragma unroll
            for (int j = 0; j < 4; ++j)
                fma_f32x2(acc[p][j], rp[p], wp[j]);
    }

    float4 b = ((const float4*)web)[db >> 2];
#pragma unroll
    for (int p = 0; p < 4; ++p) {
        int q0 = qb0 + qg * 8 + 2 * p;
        if (q0 < NQ) {
            float4 o;
            o.x = lo_f(acc[p][0]) + b.x;  o.y = lo_f(acc[p][1]) + b.y;
            o.z = lo_f(acc[p][2]) + b.z;  o.w = lo_f(acc[p][3]) + b.w;
            ((float4*)g_table)[((size_t)q0 * DD + db) >> 2] = o;
        }
        if (q0 + 1 < NQ) {
            float4 o;
            o.x = hi_f(acc[p][0]) + b.x;  o.y = hi_f(acc[p][1]) + b.y;
            o.z = hi_f(acc[p][2]) + b.z;  o.w = hi_f(acc[p][3]) + b.w;
            ((float4*)g_table)[((size_t)(q0 + 1) * DD + db) >> 2] = o;
        }
    }
}

// ---------------------------------------------------------------------------
// Phase 2: out[b][:] = table[q(b)][:] — TMA bulk-copy pipeline.
// 1 warp/block, 64 rows/block. 8 smem stages of 4 KB; 6 loads in flight;
// wait_group.read<2> makes the stage reuse distance exact (row r+6 reuses the
// buffer of row r-2, whose store's smem read is then guaranteed complete).
// Bypasses RF + L1tex lookups entirely — bounded by the LTS/DRAM cap.
__global__ void __launch_bounds__(32) k_scatter(const float* __restrict__ tt,
                                                float* __restrict__ out) {
    __shared__ __align__(16) float buf[S_STAGES][DD];   // 32 KB
    __shared__ __align__(8) unsigned long long mbar[S_STAGES];
    __shared__ int qidx[SROWS];

    int tid = threadIdx.x;
    int b0  = blockIdx.x * SROWS;

    // q indices for the block's 64 rows
#pragma unroll
    for (int i = tid; i < SROWS; i += 32) {
        float tv = __ldg(tt + b0 + i);
        int q = (int)floorf(__fdiv_rn(tv, 0.1f));   // IEEE div under any fast-math
        qidx[i] = max(0, min(q, NQ - 1));
    }
    if (tid == 0) {
#pragma unroll
        for (int s = 0; s < S_STAGES; ++s)
            mbar_init(smem_u32(&mbar[s]), 1);
        fence_proxy_async_shared();                 // init visible to async proxy
    }
    __syncwarp();

    if (tid == 0) {
        // prologue: fill the load pipeline
#pragma unroll
        for (int i = 0; i < LOOKAHEAD; ++i) {
            uint32_t mb = smem_u32(&mbar[i]);
            mbar_expect_tx(mb, DD * 4);
            bulk_g2s(smem_u32(buf[i]), g_table + (size_t)qidx[i] * DD, DD * 4, mb);
        }
        // steady state
        for (int r = 0; r < SROWS; ++r) {
            int s   = r & (S_STAGES - 1);
            int par = (r >> 3) & 1;
            mbar_wait(smem_u32(&mbar[s]), par);
            bulk_s2g(out + (size_t)(b0 + r) * DD, smem_u32(buf[s]), DD * 4);
            bulk_commit();
            int rn = r + LOOKAHEAD;
            if (rn < SROWS) {
                bulk_wait_read<2>();                // buffer (rn & 7) reads done
                int sn = rn & (S_STAGES - 1);
                uint32_t mb = smem_u32(&mbar[sn]);
                mbar_expect_tx(mb, DD * 4);
                bulk_g2s(smem_u32(buf[sn]), g_table + (size_t)qidx[rn] * DD, DD * 4, mb);
            }
        }
        bulk_wait_all();                            // all stores complete before exit
    }
}

// ---------------------------------------------------------------------------
extern "C" void kernel_launch(void* const* d_in, const int* in_sizes, int n_in,
                              void* d_out, int out_size) {
    const float* t   = (const float*)d_in[0];   // (B,)
    const float* wr  = (const float*)d_in[1];   // (R,1)
    const float* wrb = (const float*)d_in[2];   // (R,)
    const float* we  = (const float*)d_in[3];   // (D,R)
    const float* web = (const float*)d_in[4];   // (D,)
    float* out = (float*)d_out;
    int B = in_sizes[0];

    k_transpose_we<<<dim3(RR / 32, DD / 32), dim3(32, 8)>>>(we);
    k_build_table<<<dim3(NQP / 32, DD / 256), 256>>>(wr, wrb, web);
    k_scatter<<<B / SROWS, 32>>>(t, out);
}

// round 6
// speedup vs baseline: 1.1010x; 1.1010x over previous
#include <cuda_runtime.h>
#include <math.h>
#include <stdint.h>

#define NQ   10001          // distinct quantized times: floor(t/0.1), t in [0,1000)
#define NQP  10016          // padded to multiple of 32
#define DD   1024
#define RR   256
#define ROWS_PER_BLK 8      // scatter rows per block (B divisible by 8)

// Scratch (device globals — no allocation allowed)
__device__ float g_WeT[RR * DD];                       // w_expand^T [r][d] (1 MB)
__device__ __align__(128) float g_table[NQ * DD];      // LUT [q][d] (~41 MB)

// ---------------------------------------------------------------------------
// Packed fp32x2 helpers (sm_103a FFMA2)
__device__ __forceinline__ void fma_f32x2(unsigned long long& d,
                                          unsigned long long a,
                                          unsigned long long b) {
    asm("fma.rn.f32x2 %0, %1, %2, %0;" : "+l"(d) : "l"(a), "l"(b));
}
__device__ __forceinline__ unsigned long long splat_f32(float w) {
    unsigned long long r;
    asm("mov.b64 %0, {%1, %1};" : "=l"(r) : "f"(w));
    return r;
}
__device__ __forceinline__ float lo_f(unsigned long long p) {
    return __uint_as_float((unsigned int)p);
}
__device__ __forceinline__ float hi_f(unsigned long long p) {
    return __uint_as_float((unsigned int)(p >> 32));
}

// ---------------------------------------------------------------------------
// 256-bit L2 eviction-priority memory ops (sm_103a: hints require v4.b64)
__device__ __forceinline__ ulonglong4 ldg256_evict_last(const void* p) {
    ulonglong4 v;
    asm volatile("ld.global.nc.L2::evict_last.v4.b64 {%0,%1,%2,%3}, [%4];"
                 : "=l"(v.x), "=l"(v.y), "=l"(v.z), "=l"(v.w) : "l"(p));
    return v;
}
__device__ __forceinline__ void stg256_evict_first(void* p, ulonglong4 v) {
    asm volatile("st.global.L2::evict_first.v4.b64 [%0], {%1,%2,%3,%4};"
                 :: "l"(p), "l"(v.x), "l"(v.y), "l"(v.z), "l"(v.w) : "memory");
}

// ---------------------------------------------------------------------------
// Phase 0: tiled transpose w_expand (D,R) -> (R,D); coalesced both sides.
__global__ void k_transpose_we(const float* __restrict__ we) {
    __shared__ float tile[32][33];
    int tx = threadIdx.x, ty = threadIdx.y;
    int r0 = blockIdx.x * 32, d0 = blockIdx.y * 32;
#pragma unroll
    for (int k = 0; k < 32; k += 8)
        tile[ty + k][tx] = we[(d0 + ty + k) * RR + (r0 + tx)];
    __syncthreads();
#pragma unroll
    for (int k = 0; k < 32; k += 8)
        g_WeT[(r0 + ty + k) * DD + (d0 + tx)] = tile[tx][ty + k];
}

// ---------------------------------------------------------------------------
// Phase 1 (fused): red tile in smem, then table = red @ WeT + web via FFMA2.
// Block 256 thr; tile 32 q x 256 d; thread 4 q-pairs x 4 d. grid (313, 4).
__global__ void __launch_bounds__(256) k_build_table(const float* __restrict__ wr,
                                                     const float* __restrict__ wrb,
                                                     const float* __restrict__ web) {
    __shared__ float sRed[RR * 32];   // [r][q_local], 32 KB
    __shared__ float sWr[RR], sWrb[RR];

    int tid = threadIdx.x;
    int qb0 = blockIdx.x * 32;

    if (tid < RR) { sWr[tid] = wr[tid]; sWrb[tid] = wrb[tid]; }
    __syncthreads();

#pragma unroll 4
    for (int i = tid; i < RR * 32; i += 256) {
        int r  = i >> 5;
        int ql = i & 31;
        int qc = min(qb0 + ql, NQ - 1);           // pad clamped (never stored)
        float tq  = (float)qc * 0.1f;             // matches floor(t/0.1f)*0.1f
        float arg = fmaf(tq, sWr[r], sWrb[r]);
        // Cody-Waite 2*pi reduction (|arg| <= ~153): exact under fast-math
        float k   = rintf(arg * 0.15915494309189535f);
        float red = fmaf(-k, 6.28125f, arg);
        red       = fmaf(-k, 1.9353071795864769e-3f, red);
        float v   = cosf(red);
        sRed[r * 32 + ql] = v > 0.0f ? v : 0.0f;
    }
    __syncthreads();

    int dt = tid & 63;
    int qg = tid >> 6;
    int db = blockIdx.y * 256 + dt * 4;

    unsigned long long acc[4][4];
#pragma unroll
    for (int p = 0; p < 4; ++p)
#pragma unroll
        for (int j = 0; j < 4; ++j) acc[p][j] = 0ULL;

    const float4* WeT4 = (const float4*)g_WeT;
    const ulonglong2* sRed2 = (const ulonglong2*)sRed;

#pragma unroll 4
    for (int r = 0; r < RR; ++r) {
        float4 w = WeT4[(r * DD + db) >> 2];          // coalesced LDG.128
        unsigned long long wp[4] = { splat_f32(w.x), splat_f32(w.y),
                                     splat_f32(w.z), splat_f32(w.w) };
        int sb = (r * 32 + qg * 8) >> 2;              // warp-uniform broadcast
        ulonglong2 y0 = sRed2[sb];
        ulonglong2 y1 = sRed2[sb + 1];
        unsigned long long rp[4] = { y0.x, y0.y, y1.x, y1.y };
#pragma unroll
        for (int p = 0; p < 4; ++p)
#pragma unroll
            for (int j = 0; j < 4; ++j)
                fma_f32x2(acc[p][j], rp[p], wp[j]);
    }

    float4 b = ((const float4*)web)[db >> 2];
#pragma unroll
    for (int p = 0; p < 4; ++p) {
        int q0 = qb0 + qg * 8 + 2 * p;
        if (q0 < NQ) {
            float4 o;
            o.x = lo_f(acc[p][0]) + b.x;  o.y = lo_f(acc[p][1]) + b.y;
            o.z = lo_f(acc[p][2]) + b.z;  o.w = lo_f(acc[p][3]) + b.w;
            ((float4*)g_table)[((size_t)q0 * DD + db) >> 2] = o;
        }
        if (q0 + 1 < NQ) {
            float4 o;
            o.x = hi_f(acc[p][0]) + b.x;  o.y = hi_f(acc[p][1]) + b.y;
            o.z = hi_f(acc[p][2]) + b.z;  o.w = hi_f(acc[p][3]) + b.w;
            ((float4*)g_table)[((size_t)(q0 + 1) * DD + db) >> 2] = o;
        }
    }
}

// ---------------------------------------------------------------------------
// Phase 2: out[b][:] = table[q(b)][:]
// 8 rows/block, 128 threads x 32 B = one 4 KB row per step.
// 8 independent 256-bit loads (evict_last: pin table in L2), then 8 256-bit
// stores (evict_first: output stream never displaces the table).
__global__ void __launch_bounds__(128) k_scatter(const float* __restrict__ tt,
                                                 float* __restrict__ out) {
    __shared__ int qidx[ROWS_PER_BLK];
    int b0 = blockIdx.x * ROWS_PER_BLK;
    if (threadIdx.x < ROWS_PER_BLK) {
        float tv = __ldg(tt + b0 + threadIdx.x);
        int q = (int)floorf(__fdiv_rn(tv, 0.1f));   // IEEE div under any fast-math
        qidx[threadIdx.x] = max(0, min(q, NQ - 1));
    }
    __syncthreads();

    ulonglong4 v[ROWS_PER_BLK];
#pragma unroll
    for (int i = 0; i < ROWS_PER_BLK; ++i)
        v[i] = ldg256_evict_last(g_table + (size_t)qidx[i] * DD + threadIdx.x * 8);
#pragma unroll
    for (int i = 0; i < ROWS_PER_BLK; ++i)
        stg256_evict_first(out + (size_t)(b0 + i) * DD + threadIdx.x * 8, v[i]);
}

// ---------------------------------------------------------------------------
extern "C" void kernel_launch(void* const* d_in, const int* in_sizes, int n_in,
                              void* d_out, int out_size) {
    const float* t   = (const float*)d_in[0];   // (B,)
    const float* wr  = (const float*)d_in[1];   // (R,1)
    const float* wrb = (const float*)d_in[2];   // (R,)
    const float* we  = (const float*)d_in[3];   // (D,R)
    const float* web = (const float*)d_in[4];   // (D,)
    float* out = (float*)d_out;
    int B = in_sizes[0];

    k_transpose_we<<<dim3(RR / 32, DD / 32), dim3(32, 8)>>>(we);
    k_build_table<<<dim3(NQP / 32, DD / 256), 256>>>(wr, wrb, web);
    k_scatter<<<B / ROWS_PER_BLK, 128>>>(t, out);
}

// round 8
// speedup vs baseline: 1.3839x; 1.2570x over previous
#include <cuda_runtime.h>
#include <cuda_bf16.h>
#include <math.h>
#include <stdint.h>

#define NQ   10001          // distinct quantized times: floor(t/0.1), t in [0,1000)
#define DD   1024
#define RR   256
#define QT   128            // q tile (block M)
#define DT   64             // d tile (block N)
#define NQT  10112          // 79 * 128 q-tiles
#define ROWS_PER_BLK 8      // scatter rows per block
#define SP   264            // padded bf16 smem row stride (528 B: 16B-aligned, conflict-free)

// Scratch (device globals — no allocation allowed)
__device__ __nv_bfloat16 g_redH[NQT * RR];   // hi(relu(cos)) [q][r]
__device__ __nv_bfloat16 g_redL[NQT * RR];   // lo residual
__device__ __nv_bfloat16 g_WeH[DD * RR];     // hi(w_expand) [d][r] (already K-major)
__device__ __nv_bfloat16 g_WeL[DD * RR];     // lo residual
__device__ __align__(128) float g_table[NQ * DD];   // LUT [q][d], ~41 MB

// smem byte offsets (dynamic)
#define OFF_AH 0
#define OFF_AL (QT * SP * 2)                  //  67584
#define OFF_BH (2 * QT * SP * 2)              // 135168
#define OFF_BL (2 * QT * SP * 2 + DT * SP * 2)
#define SMEM_MMA (2 * QT * SP * 2 + 2 * DT * SP * 2)   // 202752 B

// ---------------------------------------------------------------------------
__device__ __forceinline__ uint32_t smem_u32(const void* p) {
    uint32_t a;
    asm("{ .reg .u64 t; cvta.to.shared.u64 t, %1; cvt.u32.u64 %0, t; }"
        : "=r"(a) : "l"(p));
    return a;
}
__device__ __forceinline__ void ldm4(uint32_t* r, uint32_t addr) {
    asm volatile("ldmatrix.sync.aligned.m8n8.x4.shared.b16 {%0,%1,%2,%3}, [%4];"
                 : "=r"(r[0]), "=r"(r[1]), "=r"(r[2]), "=r"(r[3]) : "r"(addr));
}
__device__ __forceinline__ void mma_bf16(float* c, const uint32_t* a,
                                         uint32_t b0, uint32_t b1) {
    asm volatile(
        "mma.sync.aligned.m16n8k16.row.col.f32.bf16.bf16.f32 "
        "{%0,%1,%2,%3}, {%4,%5,%6,%7}, {%8,%9}, {%0,%1,%2,%3};"
        : "+f"(c[0]), "+f"(c[1]), "+f"(c[2]), "+f"(c[3])
        : "r"(a[0]), "r"(a[1]), "r"(a[2]), "r"(a[3]), "r"(b0), "r"(b1));
}

// ---------------------------------------------------------------------------
// Prep A: red[q][r] = relu(cos(tq*wr+wrb)), split to hi/lo bf16.
__global__ void k_prep_red(const float* __restrict__ wr,
                           const float* __restrict__ wrb) {
    int q = blockIdx.x;
    int r = threadIdx.x;
    int qc = min(q, NQ - 1);                  // pad rows clamped (never stored)
    float tq  = (float)qc * 0.1f;             // matches floor(t/0.1f)*0.1f
    float arg = fmaf(tq, wr[r], wrb[r]);
    // Cody-Waite 2*pi reduction (|arg| <= ~153): exact under fast-math
    float k   = rintf(arg * 0.15915494309189535f);
    float red = fmaf(-k, 6.28125f, arg);
    red       = fmaf(-k, 1.9353071795864769e-3f, red);
    float v   = cosf(red);
    v = v > 0.0f ? v : 0.0f;
    __nv_bfloat16 h = __float2bfloat16(v);
    __nv_bfloat16 l = __float2bfloat16(v - __bfloat162float(h));
    g_redH[q * RR + r] = h;
    g_redL[q * RR + r] = l;
}

// Prep B: split w_expand [d][r] into hi/lo bf16 (already K-major).
__global__ void k_prep_we(const float* __restrict__ we) {
    int d = blockIdx.x;
    int r = threadIdx.x;
    float v = we[d * RR + r];
    __nv_bfloat16 h = __float2bfloat16(v);
    __nv_bfloat16 l = __float2bfloat16(v - __bfloat162float(h));
    g_WeH[d * RR + r] = h;
    g_WeL[d * RR + r] = l;
}

// ---------------------------------------------------------------------------
// HMMA table build: table[128q x 64d] = (redH+redL) @ (WeH+WeL)^T + web
// via 3 split-bf16 products. 8 warps (4m x 2n); warp tile 32q x 32d.
// grid (79, 16), 256 threads.
__global__ void __launch_bounds__(256) k_mma_table(const float* __restrict__ web) {
    extern __shared__ char dsm[];
    __shared__ float sWeb[DT];
    uint32_t sb = smem_u32(dsm);
    int tid = threadIdx.x, lane = tid & 31, wid = tid >> 5;
    int qt0 = blockIdx.x * QT, dt0 = blockIdx.y * DT;

    if (tid < DT) sWeb[tid] = web[dt0 + tid];

    // Stage A (128 x 256 bf16, H/L) and B (64 x 256, H/L) into padded smem.
#pragma unroll 4
    for (int i = tid; i < QT * 32; i += 256) {
        int row = i >> 5, u = i & 31;
        size_t   src = (size_t)(qt0 + row) * RR + u * 8;
        uint32_t dst = (uint32_t)(row * SP + u * 8) * 2;
        *(uint4*)(dsm + OFF_AH + dst) = *(const uint4*)(g_redH + src);
        *(uint4*)(dsm + OFF_AL + dst) = *(const uint4*)(g_redL + src);
    }
#pragma unroll 2
    for (int i = tid; i < DT * 32; i += 256) {
        int row = i >> 5, u = i & 31;
        size_t   src = (size_t)(dt0 + row) * RR + u * 8;
        uint32_t dst = (uint32_t)(row * SP + u * 8) * 2;
        *(uint4*)(dsm + OFF_BH + dst) = *(const uint4*)(g_WeH + src);
        *(uint4*)(dsm + OFF_BL + dst) = *(const uint4*)(g_WeL + src);
    }
    __syncthreads();

    int wm = wid & 3;                 // m32 group
    int wn = wid >> 2;                // n32 group
    int lrow  = lane & 15;            // ldmatrix row within 16
    int khalf = (lane >> 4) * 8;      // k half select

    uint32_t aHb = sb + OFF_AH + (uint32_t)((wm * 32 + lrow) * SP + khalf) * 2;
    uint32_t aLb = sb + OFF_AL + (uint32_t)((wm * 32 + lrow) * SP + khalf) * 2;
    uint32_t bHb = sb + OFF_BH + (uint32_t)((wn * 32 + lrow) * SP + khalf) * 2;
    uint32_t bLb = sb + OFF_BL + (uint32_t)((wn * 32 + lrow) * SP + khalf) * 2;

    float acc[2][4][4];               // [m16 tile][n8 tile][c0..c3]
#pragma unroll
    for (int m = 0; m < 2; ++m)
#pragma unroll
        for (int j = 0; j < 4; ++j)
#pragma unroll
            for (int c = 0; c < 4; ++c) acc[m][j][c] = 0.0f;

#pragma unroll
    for (int ks = 0; ks < 16; ++ks) {
        uint32_t ko = (uint32_t)(ks * 16) * 2;
        uint32_t aH[2][4], aL[2][4], bH[2][4], bL[2][4];
        ldm4(aH[0], aHb + ko);
        ldm4(aH[1], aHb + ko + 16 * SP * 2);
        ldm4(aL[0], aLb + ko);
        ldm4(aL[1], aLb + ko + 16 * SP * 2);
        ldm4(bH[0], bHb + ko);                  // n 0-15
        ldm4(bH[1], bHb + ko + 16 * SP * 2);    // n 16-31
        ldm4(bL[0], bLb + ko);
        ldm4(bL[1], bLb + ko + 16 * SP * 2);
#pragma unroll
        for (int m = 0; m < 2; ++m) {
#pragma unroll
            for (int j = 0; j < 4; ++j) {
                int g = j >> 1, p = j & 1;
                mma_bf16(acc[m][j], aH[m], bH[g][p], bH[g][p + 2]);  // hh
                mma_bf16(acc[m][j], aH[m], bL[g][p], bL[g][p + 2]);  // hl
                mma_bf16(acc[m][j], aL[m], bH[g][p], bH[g][p + 2]);  // lh
            }
        }
    }

    // Epilogue: +bias, direct fp32 stores (float2 per fragment row).
    int crow = lane >> 2;             // 0..7
    int ccol = (lane & 3) * 2;
#pragma unroll
    for (int m = 0; m < 2; ++m) {
        int r0 = qt0 + wm * 32 + m * 16 + crow;
#pragma unroll
        for (int j = 0; j < 4; ++j) {
            int cl = wn * 32 + j * 8 + ccol;
            float b0 = sWeb[cl], b1 = sWeb[cl + 1];
            if (r0 < NQ) {
                float2 o = { acc[m][j][0] + b0, acc[m][j][1] + b1 };
                *(float2*)(g_table + (size_t)r0 * DD + dt0 + cl) = o;
            }
            if (r0 + 8 < NQ) {
                float2 o = { acc[m][j][2] + b0, acc[m][j][3] + b1 };
                *(float2*)(g_table + (size_t)(r0 + 8) * DD + dt0 + cl) = o;
            }
        }
    }
}

// ---------------------------------------------------------------------------
// Scatter: out[b][:] = table[q(b)][:] — best measured config (R3).
__global__ void __launch_bounds__(256) k_scatter(const float* __restrict__ tt,
                                                 float4* __restrict__ out) {
    __shared__ int qidx[ROWS_PER_BLK];
    int b0 = blockIdx.x * ROWS_PER_BLK;
    if (threadIdx.x < ROWS_PER_BLK) {
        float tv = __ldg(tt + b0 + threadIdx.x);
        int q = (int)floorf(__fdiv_rn(tv, 0.1f));   // IEEE div under any fast-math
        qidx[threadIdx.x] = max(0, min(q, NQ - 1));
    }
    __syncthreads();

    const float4* tab = (const float4*)g_table;
    float4 v[ROWS_PER_BLK];
#pragma unroll
    for (int i = 0; i < ROWS_PER_BLK; ++i)
        v[i] = tab[(size_t)qidx[i] * (DD / 4) + threadIdx.x];
#pragma unroll
    for (int i = 0; i < ROWS_PER_BLK; ++i)
        __stcs(out + ((size_t)(b0 + i) * (DD / 4) + threadIdx.x), v[i]);
}

// ---------------------------------------------------------------------------
extern "C" void kernel_launch(void* const* d_in, const int* in_sizes, int n_in,
                              void* d_out, int out_size) {
    const float* t   = (const float*)d_in[0];   // (B,)
    const float* wr  = (const float*)d_in[1];   // (R,1)
    const float* wrb = (const float*)d_in[2];   // (R,)
    const float* we  = (const float*)d_in[3];   // (D,R)
    const float* web = (const float*)d_in[4];   // (D,)
    float* out = (float*)d_out;
    int B = in_sizes[0];

    cudaFuncSetAttribute(k_mma_table,
                         cudaFuncAttributeMaxDynamicSharedMemorySize, SMEM_MMA);

    k_prep_red<<<NQT, RR>>>(wr, wrb);
    k_prep_we<<<DD, RR>>>(we);
    k_mma_table<<<dim3(NQT / QT, DD / DT), 256, SMEM_MMA>>>(web);
    k_scatter<<<B / ROWS_PER_BLK, 256>>>(t, (float4*)out);
}